// round 5
// baseline (speedup 1.0000x reference)
#include <cuda_runtime.h>
#include <cstdint>
#include <cstddef>

#define Bv     8
#define Nv     128
#define FNv    64
#define IPC    8
#define CHUNKS 16

// ------------------------------ device scratch ------------------------------
__device__ float g_Wt[128 * 132];        // B operand [n=2l+br][k(128)+pad4], tf32 bits
                                         // k 0..63 = We rows, k 64..127 = Wj rows
__device__ float g_part[Bv * CHUNKS * Nv * FNv];

// ------------------------------ helpers ------------------------------
__device__ __forceinline__ uint32_t cvt_tf32(float x) {
    uint32_t r; asm("cvt.rna.tf32.f32 %0, %1;" : "=r"(r) : "f"(x)); return r;
}
__device__ __forceinline__ uint32_t smem_u32(const void* p) {
    uint32_t a;
    asm("{ .reg .u64 t; cvta.to.shared.u64 t, %1; cvt.u32.u64 %0, t; }" : "=r"(a) : "l"(p));
    return a;
}
__device__ __forceinline__ void cp16(uint32_t dst, const void* src) {
    asm volatile("cp.async.cg.shared.global [%0], [%1], 16;" :: "r"(dst), "l"(src) : "memory");
}
__device__ __forceinline__ void cp_commit() {
    asm volatile("cp.async.commit_group;" ::: "memory");
}
template <int N>
__device__ __forceinline__ void cp_wait() {
    asm volatile("cp.async.wait_group %0;" :: "n"(N) : "memory");
}
__device__ __forceinline__ void mma8(float* c, const uint32_t* a, const uint32_t* b) {
    asm volatile(
        "mma.sync.aligned.m16n8k8.row.col.f32.tf32.tf32.f32 "
        "{%0,%1,%2,%3}, {%4,%5,%6,%7}, {%8,%9}, {%0,%1,%2,%3};"
        : "+f"(c[0]), "+f"(c[1]), "+f"(c[2]), "+f"(c[3])
        : "r"(a[0]), "r"(a[1]), "r"(a[2]), "r"(a[3]), "r"(b[0]), "r"(b[1]));
}

// ------------------------------ weight prep ------------------------------
// 16896 values, one per thread. n = 2l+br; k<64 -> We row (128+k); 64<=k<128 -> W row k (Wj).
__global__ void __launch_bounds__(256)
wprep_kernel(const float* __restrict__ Watt, const float* __restrict__ Wnei) {
    const int idx = blockIdx.x * 256 + threadIdx.x;      // < 16896 = 66*256
    const int n = idx / 132, k = idx % 132;
    const int l = n >> 1, br = n & 1;
    float val = 0.f;
    if (k < 128) {
        const float* __restrict__ W = br ? Wnei : Watt;
        const int row = (k < 64) ? (128 + k) : k;
        val = W[row * 64 + l];
    }
    g_Wt[idx] = __uint_as_float(cvt_tf32(val));
}

// ------------------------------ main kernel ------------------------------
#define EROW   68
#define WROW   132
#define EBUF   (128 * EROW * 4)          // 34816
#define PJROW  68                         // float2 units (544 B rows)
#define OFF_W  0                          // 67584
#define OFF_E  67584                      // 2 x 34816 (buf1 doubles as H tile pre-loop)
#define OFF_PJ 137216                     // 69632
#define OFF_PI 206848                     // 4096
#define OFF_A  210944                     // 4096
#define SMEM_DYN (215040 + 1024)

__global__ void __launch_bounds__(256, 1)
main_kernel(const float* __restrict__ A,
            const float* __restrict__ E,
            const float* __restrict__ H,
            const float* __restrict__ Watt,
            const float* __restrict__ Wnei,
            const float* __restrict__ biasA,
            const float* __restrict__ biasN) {
    extern __shared__ char smraw[];
    char* sm = (char*)(((uintptr_t)smraw + 1023) & ~(uintptr_t)1023);
    const uint32_t sb = smem_u32(sm);

    const int t = threadIdx.x, lane = t & 31, wid = t >> 5;
    const int g = lane >> 2, tg = lane & 3;
    const int b = blockIdx.x >> 4, chunk = blockIdx.x & 15, i0 = chunk * IPC;
    const int mbase = (wid & 3) * 32;
    const int wn    = wid >> 2;
    const int lbase = wn * 32;
    const int nrow0 = wn * 64;

    // ---- group 0a: W' + H tile (H overlays E buf1) ----
    {
        #pragma unroll
        for (int v = 0; v < 17; v++) {
            const int n = v * 256 + t;
            if (n < 4224) cp16(sb + OFF_W + n * 16, (const char*)g_Wt + n * 16);
        }
        const char* Hg = (const char*)(H + (size_t)b * Nv * FNv);
        #pragma unroll
        for (int v = 0; v < 8; v++) {
            const int n = v * 256 + t, row = n >> 4, c = n & 15;
            cp16(sb + OFF_E + EBUF + row * 272 + c * 16, Hg + n * 16);
        }
        cp_commit();
    }
    // ---- group 0b: E tile 0 + A chunk ----
    {
        const char* Eg = (const char*)(E + ((size_t)(b * Nv + i0)) * Nv * FNv);
        #pragma unroll
        for (int v = 0; v < 8; v++) {
            const int n = v * 256 + t, row = n >> 4, c = n & 15;
            cp16(sb + OFF_E + row * 272 + c * 16, Eg + n * 16);
        }
        cp16(sb + OFF_A + t * 16, (const char*)(A + (size_t)(b * Nv + i0) * Nv) + t * 16);
        cp_commit();
    }

    float brA[8], brN[8];
    #pragma unroll
    for (int nt = 0; nt < 8; nt++) {
        brA[nt] = __ldg(biasA + lbase + nt * 4 + tg);
        brN[nt] = __ldg(biasN + lbase + nt * 4 + tg);
    }

    cp_wait<1>();        // group 0a (W' + H) resident
    __syncthreads();

    // ---- Pj GEMM: Pj[j,n] = sum_f H[j,f] * Wj'[f,n]  (B rows k=64..127) ----
    {
        const float*    __restrict__ Hb = (const float*)(sm + OFF_E + EBUF);
        const uint32_t* __restrict__ Wb = (const uint32_t*)(sm + OFF_W);
        float c[2][8][4];
        #pragma unroll
        for (int mt = 0; mt < 2; mt++)
            #pragma unroll
            for (int nt = 0; nt < 8; nt++)
                #pragma unroll
                for (int q = 0; q < 4; q++) c[mt][nt][q] = 0.f;

        #pragma unroll
        for (int ks = 0; ks < 8; ks++) {
            const int k0 = ks * 8;
            uint32_t a[2][4];
            #pragma unroll
            for (int mt = 0; mt < 2; mt++) {
                const float* ap = Hb + (mbase + mt * 16 + g) * EROW + k0 + tg;
                a[mt][0] = cvt_tf32(ap[0]);
                a[mt][1] = cvt_tf32(ap[8 * EROW]);
                a[mt][2] = cvt_tf32(ap[4]);
                a[mt][3] = cvt_tf32(ap[8 * EROW + 4]);
            }
            uint32_t bf[8][2];
            #pragma unroll
            for (int nt = 0; nt < 8; nt++) {
                const uint32_t* bp = Wb + (nrow0 + nt * 8 + g) * WROW + 64 + k0 + tg;
                bf[nt][0] = bp[0];
                bf[nt][1] = bp[4];
            }
            #pragma unroll
            for (int mt = 0; mt < 2; mt++)
                #pragma unroll
                for (int nt = 0; nt < 8; nt++)
                    mma8(c[mt][nt], a[mt], bf[nt]);
        }
        float2* __restrict__ PJs = (float2*)(sm + OFF_PJ);
        #pragma unroll
        for (int mt = 0; mt < 2; mt++) {
            const int j0 = mbase + mt * 16 + g;
            #pragma unroll
            for (int nt = 0; nt < 8; nt++) {
                const int l = lbase + nt * 4 + tg;
                PJs[(size_t)j0 * PJROW + l]       = make_float2(c[mt][nt][0], c[mt][nt][1]);
                PJs[(size_t)(j0 + 8) * PJROW + l] = make_float2(c[mt][nt][2], c[mt][nt][3]);
            }
        }
    }

    // ---- Pi (scalar): warp wid handles i = i0+wid; lane covers l=lane, lane+32 ----
    {
        const float* __restrict__ Hrow = (const float*)(sm + OFF_E + EBUF) + (i0 + wid) * EROW;
        float aA0 = 0.f, aA1 = 0.f, aN0 = 0.f, aN1 = 0.f;
        #pragma unroll 8
        for (int f = 0; f < 64; f++) {
            const float h = Hrow[f];
            aA0 = fmaf(h, __ldg(Watt + f * 64 + lane),      aA0);
            aA1 = fmaf(h, __ldg(Watt + f * 64 + lane + 32), aA1);
            aN0 = fmaf(h, __ldg(Wnei + f * 64 + lane),      aN0);
            aN1 = fmaf(h, __ldg(Wnei + f * 64 + lane + 32), aN1);
        }
        float2* __restrict__ Pis = (float2*)(sm + OFF_PI);
        Pis[wid * 64 + lane]      = make_float2(aA0, aN0);
        Pis[wid * 64 + lane + 32] = make_float2(aA1, aN1);
    }
    __syncthreads();     // PJ/Pi written; H-tile reads done -> buf1 reusable

    float outacc[2][2][8];
    #pragma unroll
    for (int mt = 0; mt < 2; mt++)
        #pragma unroll
        for (int h = 0; h < 2; h++)
            #pragma unroll
            for (int nt = 0; nt < 8; nt++) outacc[mt][h][nt] = 0.f;

    for (int ii = 0; ii < IPC; ii++) {
        if (ii + 1 < IPC) {
            const char* Eg = (const char*)(E + ((size_t)(b * Nv + i0 + ii + 1)) * Nv * FNv);
            const uint32_t dstb = sb + OFF_E + ((ii + 1) & 1) * EBUF;
            #pragma unroll
            for (int v = 0; v < 8; v++) {
                const int n = v * 256 + t, row = n >> 4, c = n & 15;
                cp16(dstb + row * 272 + c * 16, Eg + n * 16);
            }
            cp_commit();
            cp_wait<1>();
        } else {
            cp_wait<0>();
        }
        __syncthreads();

        const float*    __restrict__ Eb = (const float*)(sm + OFF_E + (ii & 1) * EBUF);
        const uint32_t* __restrict__ Wb = (const uint32_t*)(sm + OFF_W);

        float c[2][8][4];
        #pragma unroll
        for (int mt = 0; mt < 2; mt++)
            #pragma unroll
            for (int nt = 0; nt < 8; nt++)
                #pragma unroll
                for (int q = 0; q < 4; q++) c[mt][nt][q] = 0.f;

        #pragma unroll
        for (int ks = 0; ks < 8; ks++) {
            const int k0 = ks * 8;
            uint32_t a[2][4];
            #pragma unroll
            for (int mt = 0; mt < 2; mt++) {
                const float* ap = Eb + (mbase + mt * 16 + g) * EROW + k0 + tg;
                a[mt][0] = cvt_tf32(ap[0]);
                a[mt][1] = cvt_tf32(ap[8 * EROW]);
                a[mt][2] = cvt_tf32(ap[4]);
                a[mt][3] = cvt_tf32(ap[8 * EROW + 4]);
            }
            uint32_t bf[8][2];
            #pragma unroll
            for (int nt = 0; nt < 8; nt++) {
                const uint32_t* bp = Wb + (nrow0 + nt * 8 + g) * WROW + k0 + tg;
                bf[nt][0] = bp[0];
                bf[nt][1] = bp[4];
            }
            #pragma unroll
            for (int mt = 0; mt < 2; mt++)
                #pragma unroll
                for (int nt = 0; nt < 8; nt++)
                    mma8(c[mt][nt], a[mt], bf[nt]);
        }
        __syncthreads();

        // ---- epilogue ----
        const float*  __restrict__ As_i = (const float*)(sm + OFF_A) + ii * 128;
        const float2* __restrict__ Pi_i = (const float2*)(sm + OFF_PI) + ii * 64;
        const float2* __restrict__ Pjs  = (const float2*)(sm + OFF_PJ);

        #pragma unroll
        for (int mt = 0; mt < 2; mt++) {
            const int j0 = mbase + mt * 16 + g;
            const float a0 = As_i[j0], a1 = As_i[j0 + 8];
            const float2* pr0 = Pjs + (size_t)j0 * PJROW;
            const float2* pr1 = pr0 + 8 * PJROW;
            #pragma unroll
            for (int nt = 0; nt < 8; nt++) {
                const int l = lbase + nt * 4 + tg;
                const float2 pi = Pi_i[l];
                const float2 q0 = pr0[l];
                const float2 q1 = pr1[l];
                {
                    const float att = fmaf(a0, c[mt][nt][0] + pi.x + q0.x, brA[nt]);
                    const float cv  = fmaf(a0, c[mt][nt][1] + pi.y + q0.y, brN[nt]);
                    float th; asm("tanh.approx.f32 %0, %1;" : "=f"(th) : "f"(att * 0.5f));
                    outacc[mt][0][nt] = fmaf(fmaxf(cv, 0.f), fmaf(0.5f, th, 0.5f),
                                             outacc[mt][0][nt]);
                }
                {
                    const float att = fmaf(a1, c[mt][nt][2] + pi.x + q1.x, brA[nt]);
                    const float cv  = fmaf(a1, c[mt][nt][3] + pi.y + q1.y, brN[nt]);
                    float th; asm("tanh.approx.f32 %0, %1;" : "=f"(th) : "f"(att * 0.5f));
                    outacc[mt][1][nt] = fmaf(fmaxf(cv, 0.f), fmaf(0.5f, th, 0.5f),
                                             outacc[mt][1][nt]);
                }
            }
        }
    }

    // ---- store partials ----
    float* __restrict__ dst = g_part + (size_t)blockIdx.x * Nv * FNv;
    #pragma unroll
    for (int mt = 0; mt < 2; mt++)
        #pragma unroll
        for (int h = 0; h < 2; h++) {
            const int j = mbase + mt * 16 + h * 8 + g;
            #pragma unroll
            for (int nt = 0; nt < 8; nt++) {
                const int l = lbase + nt * 4 + tg;
                dst[j * FNv + l] = outacc[mt][h][nt];
            }
        }
}

// ------------------------------ reduce kernel ------------------------------
__global__ void __launch_bounds__(256)
reduce_kernel(float* __restrict__ out) {
    const int f4 = blockIdx.x * 256 + threadIdx.x;
    const int b = f4 >> 11;
    const int r = f4 & 2047;
    const float4* P = (const float4*)g_part;
    float4 s = make_float4(0.f, 0.f, 0.f, 0.f);
    #pragma unroll
    for (int c = 0; c < CHUNKS; c++) {
        const float4 v = P[((size_t)(b * CHUNKS + c)) * 2048 + r];
        s.x += v.x; s.y += v.y; s.z += v.z; s.w += v.w;
    }
    ((float4*)out)[b * 2048 + r] = s;
}

// ------------------------------ launch ------------------------------
extern "C" void kernel_launch(void* const* d_in, const int* in_sizes, int n_in,
                              void* d_out, int out_size) {
    const float* H    = (const float*)d_in[0];
    const float* A    = (const float*)d_in[1];
    const float* E    = (const float*)d_in[2];
    const float* Watt = (const float*)d_in[3];
    const float* Wnei = (const float*)d_in[4];
    const float* bAtt = (const float*)d_in[5];
    const float* bNei = (const float*)d_in[6];
    float* out = (float*)d_out;

    cudaFuncSetAttribute(main_kernel, cudaFuncAttributeMaxDynamicSharedMemorySize, SMEM_DYN);

    wprep_kernel<<<66, 256>>>(Watt, Wnei);
    main_kernel<<<Bv * CHUNKS, 256, SMEM_DYN>>>(A, E, H, Watt, Wnei, bAtt, bNei);
    reduce_kernel<<<64, 256>>>(out);
}